// round 14
// baseline (speedup 1.0000x reference)
#include <cuda_runtime.h>

#define SQH 0.7071067811865476f
#define CS 1032   // k4 channel stride (floats); data at [c*CS+4, c*CS+4+Ll)

// ---------------- scratch (static device globals; no allocation) -------------
__device__ float g_v[16 * 16 * 2048];        // v[b][k][l]
__device__ float g_det[491520];              // details, levels 0..3 packed
__device__ float g_app[491520];              // approxs, levels 0..3 packed
__device__ float g_cur0[512 * 16 * 128];     // dense output [dk][b][t]
__device__ float g_curk[16 * 32 * 16 * 2048];// per-k recon [b][d][k][l]

__device__ __forceinline__ int lvl_off(int lev) { return 524288 - (524288 >> lev); }

// ---------------- K1: front-end  v[b,k,l] = sum_D relu(h)*der ---------------
// (R9-proven) One block = 128 l's of one b. z staged in smem (33-pad),
// Wh in 16KB tiles. Thread = (lt, qh in {0,1}): owns one l and 8 of 16 q's.
__global__ void __launch_bounds__(256) k1_front(
    const float* __restrict__ seq, const float* __restrict__ coeffs,
    const float* __restrict__ tarr, const float* __restrict__ ts,
    const float* __restrict__ Wg, const float* __restrict__ Wh)
{
    __shared__ __align__(16) float zs[128 * 33];
    __shared__ __align__(16) float ws[4096];

    int b   = blockIdx.x >> 4;
    int l0  = (blockIdx.x & 15) * 128;
    int tid = threadIdx.x;
    int lt  = tid & 127, qh = tid >> 7;
    int l   = l0 + lt;

    // searchsorted(ts, t, 'right') - 1, clipped to [0, L-2]
    float t = __ldg(tarr + l);
    int lo = 0, hi = 2048;
    while (lo < hi) { int m = (lo + hi) >> 1; if (__ldg(ts + m) <= t) lo = m + 1; else hi = m; }
    int i = max(0, min(lo - 1, 2046));
    float invdt = 1.0f / (__ldg(ts + i + 1) - __ldg(ts + i));

    const float* srow = seq    + ((size_t)b * 2048 + l) * 64;
    const float* c0   = coeffs + ((size_t)b * 2048 + i) * 64;

    // -------- phase A: z-half (16 values) for this thread's l --------
    float za[16];
#pragma unroll
    for (int j = 0; j < 16; j++) za[j] = 0.f;
    for (int Dd = 0; Dd < 64; Dd++) {
        float s = __ldg(srow + Dd);
        const float4* wg4 = (const float4*)(Wg + Dd * 32 + qh * 16);
#pragma unroll
        for (int c = 0; c < 4; c++) {
            float4 w = __ldg(wg4 + c);
            za[c*4+0] += s * w.x; za[c*4+1] += s * w.y;
            za[c*4+2] += s * w.z; za[c*4+3] += s * w.w;
        }
    }
#pragma unroll
    for (int j = 0; j < 16; j++) zs[lt * 33 + qh * 16 + j] = fmaxf(za[j], 0.f);
    __syncthreads();

    float z[32];
#pragma unroll
    for (int dd = 0; dd < 32; dd++) z[dd] = zs[lt * 33 + dd];

    float vacc[8];
#pragma unroll
    for (int q = 0; q < 8; q++) vacc[q] = 0.f;

    // -------- phase B: 8 Dd-tiles of 8, Wh tile in smem --------
    for (int tile = 0; tile < 8; tile++) {
        __syncthreads();
        for (int idx = tid; idx < 4096; idx += 256) {
            int dd = idx >> 7, rem = idx & 127;
            ws[idx] = __ldg(Wh + (size_t)dd * 1024 + tile * 128 + rem);
        }
        __syncthreads();

#pragma unroll
        for (int dloc = 0; dloc < 8; dloc++) {
            int Dd = tile * 8 + dloc;
            float der = (__ldg(c0 + 64 + Dd) - __ldg(c0 + Dd)) * invdt;
            unsigned long long h0 = 0ULL, h1 = 0ULL, h2 = 0ULL, h3 = 0ULL;
            const float* wbase = ws + dloc * 16 + qh * 8;
#pragma unroll
            for (int dd = 0; dd < 32; dd++) {
                unsigned long long zz;
                unsigned int zu = __float_as_uint(z[dd]);
                asm("mov.b64 %0, {%1, %1};" : "=l"(zz) : "r"(zu));
                const ulonglong2* wp = (const ulonglong2*)(wbase + dd * 128);
                ulonglong2 wA = wp[0], wB = wp[1];
                asm("fma.rn.f32x2 %0, %1, %2, %0;" : "+l"(h0) : "l"(wA.x), "l"(zz));
                asm("fma.rn.f32x2 %0, %1, %2, %0;" : "+l"(h1) : "l"(wA.y), "l"(zz));
                asm("fma.rn.f32x2 %0, %1, %2, %0;" : "+l"(h2) : "l"(wB.x), "l"(zz));
                asm("fma.rn.f32x2 %0, %1, %2, %0;" : "+l"(h3) : "l"(wB.y), "l"(zz));
            }
            unsigned int u0, u1;
            float hf[8];
            asm("mov.b64 {%0, %1}, %2;" : "=r"(u0), "=r"(u1) : "l"(h0));
            hf[0] = __uint_as_float(u0); hf[1] = __uint_as_float(u1);
            asm("mov.b64 {%0, %1}, %2;" : "=r"(u0), "=r"(u1) : "l"(h1));
            hf[2] = __uint_as_float(u0); hf[3] = __uint_as_float(u1);
            asm("mov.b64 {%0, %1}, %2;" : "=r"(u0), "=r"(u1) : "l"(h2));
            hf[4] = __uint_as_float(u0); hf[5] = __uint_as_float(u1);
            asm("mov.b64 {%0, %1}, %2;" : "=r"(u0), "=r"(u1) : "l"(h3));
            hf[6] = __uint_as_float(u0); hf[7] = __uint_as_float(u1);
#pragma unroll
            for (int q = 0; q < 8; q++) vacc[q] += fmaxf(hf[q], 0.f) * der;
        }
    }

#pragma unroll
    for (int q = 0; q < 8; q++)
        g_v[((size_t)b * 16 + qh * 8 + q) * 2048 + l] = vacc[q];
}

// ---------------- K2: 4-level Haar analysis per (b,k) -----------------------
__global__ void __launch_bounds__(256) k2_haar()
{
    __shared__ float buf[2048];
    int bk  = blockIdx.x;
    int tid = threadIdx.x;
    const float* src = g_v + (size_t)bk * 2048;
    for (int t = tid; t < 2048; t += 256) buf[t] = src[t];
    __syncthreads();

    int len = 2048;
    for (int lev = 0; lev < 4; lev++) {
        int half = len >> 1;
        int off  = lvl_off(lev);
        float ca_loc[4];
#pragma unroll
        for (int j = 0; j < 4; j++) {
            int t = tid + j * 256;
            if (t < half) {
                float a = buf[2*t], c = buf[2*t + 1];
                float ca = (a + c) * SQH, cd = (a - c) * SQH;
                g_det[off + (size_t)bk * half + t] = cd;
                ca_loc[j] = ca;
            }
        }
        __syncthreads();
#pragma unroll
        for (int j = 0; j < 4; j++) {
            int t = tid + j * 256;
            if (t < half) {
                buf[t] = ca_loc[j];
                g_app[off + (size_t)bk * half + t] = ca_loc[j];
            }
        }
        __syncthreads();
        len = half;
    }
}

// ---------------- K3: 3 x (128x128) matvec stack per (d,k) over 16 batches --
__global__ void __launch_bounds__(128) k3_dense(const float* __restrict__ dW)
{
    __shared__ float xs[16 * 128];
    int dk  = blockIdx.x;
    int kk  = dk & 15;
    int tid = threadIdx.x;
    int aoff = 458752;

#pragma unroll
    for (int b = 0; b < 16; b++)
        xs[tid * 16 + b] = g_app[aoff + (size_t)(b * 16 + kk) * 128 + tid];
    __syncthreads();

    for (int j = 0; j < 3; j++) {
        const float4* wrow4 = (const float4*)(dW + ((size_t)j * 512 + dk) * 16384 + (size_t)tid * 128);
        float acc[16];
#pragma unroll
        for (int b = 0; b < 16; b++) acc[b] = 0.f;
#pragma unroll 4
        for (int q4 = 0; q4 < 32; q4++) {
            float4 w = __ldg(wrow4 + q4);
            float wv[4] = {w.x, w.y, w.z, w.w};
#pragma unroll
            for (int c = 0; c < 4; c++) {
                const float4* x4 = (const float4*)(xs + (q4 * 4 + c) * 16);
#pragma unroll
                for (int b4 = 0; b4 < 4; b4++) {
                    float4 x = x4[b4];
                    acc[b4*4+0] += wv[c] * x.x; acc[b4*4+1] += wv[c] * x.y;
                    acc[b4*4+2] += wv[c] * x.z; acc[b4*4+3] += wv[c] * x.w;
                }
            }
        }
        __syncthreads();
#pragma unroll
        for (int b = 0; b < 16; b++) xs[tid * 16 + b] = acc[b];
        __syncthreads();
    }
#pragma unroll
    for (int b = 0; b < 16; b++)
        g_cur0[((size_t)dk * 16 + b) * 128 + tid] = xs[tid * 16 + b];
}

// ---------------- K4: LC + Haar reconstruction, one block per (b,d,k) -------
// R12-proven structure. ONLY change vs R12: lev0/1 conv chunks widened to 8
// outputs processed as two 4-output halves through conv4() (verbatim R12
// arithmetic); the halves share weight loads and overlap window registers.
// Channel c data at chX[c*CS + 4 + t]; halo [2,3] and [4+Ll,5+Ll] = 0.
// wsm layout: [j][o][s][i][8] (taps 0..4 used, 5..7 zero).
__device__ __forceinline__ float4 conv4(
    float4 a0, float4 a1, float4 a2,
    float4 e0, float4 e1, float4 e2,
    const float* wA, const float* wB, float bb)
{
    float y0[12] = {a0.x,a0.y,a0.z,a0.w, a1.x,a1.y,a1.z,a1.w, a2.x,a2.y,a2.z,a2.w};
    float y1[12] = {e0.x,e0.y,e0.z,e0.w, e1.x,e1.y,e1.z,e1.w, e2.x,e2.y,e2.z,e2.w};
    float out[4];
#pragma unroll
    for (int cc = 0; cc < 4; cc++) {
        float acc = bb;
#pragma unroll
        for (int f = 0; f < 5; f++)
            acc += wA[f] * y0[cc + f + 2] + wB[f] * y1[cc + f + 2];
        out[cc] = fmaxf(acc, 0.f);
    }
    return make_float4(out[0], out[1], out[2], out[3]);
}

template<int LEV>
__device__ __forceinline__ float* lc3_run(float* chA, float* chB,
    const float* __restrict__ wsm, const float* __restrict__ bsm, int tid)
{
    constexpr int Ll  = 2048 >> (LEV + 1);
    constexpr int SEG = 7 - LEV;
    constexpr int C   = (LEV <= 1) ? 8 : 4;  // outputs per chunk (C <= R, C | Ll)
    constexpr int NCH = 2 * Ll / C;

    float* src = chA; float* dst = chB;
#pragma unroll
    for (int j = 0; j < 3; j++) {
        const float* wj = wsm + j * 256;
        const float* bj = bsm + j * 16;
        for (int ch = tid; ch < NCH; ch += 256) {
            int ot0 = ch * C;
            int o   = (ot0 >= Ll) ? 1 : 0;
            int t0  = ot0 - o * Ll;
            int s   = t0 >> SEG;
            float bb = bj[o * 8 + s];

            const float4* wp = (const float4*)(wj + (o * 8 + s) * 16);
            float4 wa0 = wp[0], wa1 = wp[1], wb0 = wp[2], wb1 = wp[3];
            float wA[5] = {wa0.x, wa0.y, wa0.z, wa0.w, wa1.x};
            float wB[5] = {wb0.x, wb0.y, wb0.z, wb0.w, wb1.x};

            const float4* s0 = (const float4*)(src + t0);
            const float4* s1 = (const float4*)(src + CS + t0);
            float4 a0 = s0[0], a1 = s0[1], a2 = s0[2];
            float4 e0 = s1[0], e1 = s1[1], e2 = s1[2];
            float4* dp = (float4*)(dst + o * CS + 4 + t0);
            dp[0] = conv4(a0, a1, a2, e0, e1, e2, wA, wB, bb);
            if constexpr (C == 8) {
                // half 1: outputs t0+4..t0+7 need src[t0+6 .. t0+13] ⊂ {a1,a2,a3}
                float4 a3 = s0[3], e3 = s1[3];
                dp[1] = conv4(a1, a2, a3, e1, e2, e3, wA, wB, bb);
            }
        }
        __syncthreads();
        float* tp = src; src = dst; dst = tp;
    }
    return src;   // = chB (3 swaps)
}

template<int LEV>
__device__ __forceinline__ void k4_level(
    float* cur, float* chA, float* chB, float* wsm, float* bsm,
    const float* lcw, const float* lcb, int b, int dd, int kk, int tid)
{
    constexpr int Ll  = 2048 >> (LEV + 1);
    constexpr int OFF = 524288 - (524288 >> LEV);
    size_t cbase = (size_t)OFF + (size_t)(b * 16 + kk) * Ll;

    // zero halos of both buffers, both channels
    if (tid < 8) {
        int c = tid >> 2, u = tid & 3;
        int idx = c * CS + ((u < 2) ? (2 + u) : (Ll + 2 + u));
        chA[idx] = 0.f; chB[idx] = 0.f;
    }
    // stage inputs: channel 0 = detail, channel 1 = approx (scalar, R9 form)
    for (int t = tid; t < Ll; t += 256) {
        chA[4 + t]      = g_det[cbase + t];
        chA[CS + 4 + t] = g_app[cbase + t];
    }
    // stage weights (padded to 8 taps) + biases
    for (int idx = tid; idx < 768; idx += 256) {
        int j   = idx >> 8;
        int rem = idx & 255;
        int os  = rem >> 4;
        int ii  = (rem >> 3) & 1;
        int f   = rem & 7;
        int o   = os >> 3, s = os & 7;
        float v = 0.f;
        if (f < 5)
            v = __ldg(lcw + (size_t)(((LEV * 3 + j) * 32 + dd) * 16 + kk) * 160
                          + ((o * 2 + ii) * 8 + s) * 5 + f);
        wsm[idx] = v;
    }
    if (tid < 48) {
        int j = tid >> 4, r = tid & 15;
        bsm[tid] = __ldg(lcb + (size_t)(((LEV * 3 + j) * 32 + dd) * 16 + kk) * 16 + r);
    }
    __syncthreads();

    float* src = lc3_run<LEV>(chA, chB, wsm, bsm, tid);

    // X[approx] += cur ; haar_rec -> chA (flat, float2), then into cur
    for (int t = tid; t < Ll; t += 256) {
        float cAv = src[CS + 4 + t] + cur[t];
        float cDv = src[4 + t];
        ((float2*)chA)[t] = make_float2((cAv + cDv) * SQH, (cAv - cDv) * SQH);
    }
    __syncthreads();
    for (int i = tid; i < (Ll >> 1); i += 256)
        ((float4*)cur)[i] = ((const float4*)chA)[i];
    __syncthreads();
}

__global__ void __launch_bounds__(256) k4_rec(
    const float* __restrict__ lcw, const float* __restrict__ lcb)
{
    __shared__ __align__(16) float cur[2048];
    __shared__ __align__(16) float chA[2 * CS];
    __shared__ __align__(16) float chB[2 * CS];
    __shared__ __align__(16) float wsm[768];
    __shared__ float bsm[48];

    int bid = blockIdx.x;
    int dd  = bid & 31;
    int kk  = (bid >> 5) & 15;
    int b   = bid >> 9;
    int tid = threadIdx.x;

    if (tid < 128)
        cur[tid] = g_cur0[((size_t)(dd * 16 + kk) * 16 + b) * 128 + tid];

    k4_level<3>(cur, chA, chB, wsm, bsm, lcw, lcb, b, dd, kk, tid);
    k4_level<2>(cur, chA, chB, wsm, bsm, lcw, lcb, b, dd, kk, tid);
    k4_level<1>(cur, chA, chB, wsm, bsm, lcw, lcb, b, dd, kk, tid);
    k4_level<0>(cur, chA, chB, wsm, bsm, lcw, lcb, b, dd, kk, tid);

    float* dst = g_curk + ((size_t)(b * 32 + dd) * 16 + kk) * 2048;
    for (int i = tid; i < 512; i += 256)
        ((float4*)dst)[i] = ((const float4*)cur)[i];
}

// ---------------- K5: sum over k, then U[b,l,:] = out[b,:,l]^T @ Wrev -------
// (R9-proven scalar version)
__global__ void __launch_bounds__(256) k5_out(
    const float* __restrict__ Wrev, float* __restrict__ U)
{
    __shared__ float ws[2048];
    __shared__ float os[32][132];
    int b   = blockIdx.y;
    int l0  = blockIdx.x * 128;
    int tid = threadIdx.x;

    for (int i = tid; i < 2048; i += 256) ws[i] = __ldg(Wrev + i);
    for (int i = tid; i < 4096; i += 256) {
        int dd = i >> 7, lt = i & 127;
        const float* p = g_curk + ((size_t)(b * 32 + dd) * 16) * 2048 + l0 + lt;
        float s = 0.f;
#pragma unroll
        for (int kk = 0; kk < 16; kk++) s += p[(size_t)kk * 2048];
        os[dd][lt] = s;
    }
    __syncthreads();

    int lt = tid >> 1, half = tid & 1;
    float acc[32];
#pragma unroll
    for (int j = 0; j < 32; j++) acc[j] = 0.f;
    for (int dd = 0; dd < 32; dd++) {
        float xv = os[dd][lt];
        const float* w = ws + dd * 64 + half * 32;
#pragma unroll
        for (int j = 0; j < 32; j++) acc[j] += xv * w[j];
    }
    float* dst = U + ((size_t)b * 2048 + l0 + lt) * 64 + half * 32;
#pragma unroll
    for (int j = 0; j < 32; j++) dst[j] = acc[j];
}

// ---------------- launch ----------------------------------------------------
extern "C" void kernel_launch(void* const* d_in, const int* in_sizes, int n_in,
                              void* d_out, int out_size)
{
    const float* seq    = (const float*)d_in[0];
    const float* coeffs = (const float*)d_in[1];
    const float* time_  = (const float*)d_in[2];
    const float* tstep  = (const float*)d_in[3];
    const float* Wg     = (const float*)d_in[4];
    const float* Wh     = (const float*)d_in[5];
    const float* dW     = (const float*)d_in[6];
    const float* lcw    = (const float*)d_in[7];
    const float* lcb    = (const float*)d_in[8];
    const float* Wrev   = (const float*)d_in[9];
    float* U = (float*)d_out;

    k1_front<<<256, 256>>>(seq, coeffs, time_, tstep, Wg, Wh);
    k2_haar<<<256, 256>>>();
    k3_dense<<<512, 128>>>(dW);
    k4_rec<<<8192, 256>>>(lcw, lcb);
    k5_out<<<dim3(16, 16), 256>>>(Wrev, U);
}

// round 16
// speedup vs baseline: 1.0729x; 1.0729x over previous
#include <cuda_runtime.h>

#define SQH 0.7071067811865476f
#define CS 1032   // k4 channel stride (floats); data at [c*CS+4, c*CS+4+Ll)

// ---------------- scratch (static device globals; no allocation) -------------
__device__ float g_v[16 * 16 * 2048];        // v[b][k][l]
__device__ float g_det[491520];              // details, levels 0..3 packed
__device__ float g_app[491520];              // approxs, levels 0..3 packed
__device__ float g_cur0[512 * 16 * 128];     // dense output [dk][b][t]
__device__ float g_curk[16 * 32 * 16 * 2048];// per-k recon [b][d][k][l]

__device__ __forceinline__ int lvl_off(int lev) { return 524288 - (524288 >> lev); }

// ---------------- K1: front-end  v[b,k,l] = sum_D relu(h)*der ---------------
// (R9-proven) One block = 128 l's of one b. z staged in smem (33-pad),
// Wh in 16KB tiles. Thread = (lt, qh in {0,1}): owns one l and 8 of 16 q's.
__global__ void __launch_bounds__(256) k1_front(
    const float* __restrict__ seq, const float* __restrict__ coeffs,
    const float* __restrict__ tarr, const float* __restrict__ ts,
    const float* __restrict__ Wg, const float* __restrict__ Wh)
{
    __shared__ __align__(16) float zs[128 * 33];
    __shared__ __align__(16) float ws[4096];

    int b   = blockIdx.x >> 4;
    int l0  = (blockIdx.x & 15) * 128;
    int tid = threadIdx.x;
    int lt  = tid & 127, qh = tid >> 7;
    int l   = l0 + lt;

    // searchsorted(ts, t, 'right') - 1, clipped to [0, L-2]
    float t = __ldg(tarr + l);
    int lo = 0, hi = 2048;
    while (lo < hi) { int m = (lo + hi) >> 1; if (__ldg(ts + m) <= t) lo = m + 1; else hi = m; }
    int i = max(0, min(lo - 1, 2046));
    float invdt = 1.0f / (__ldg(ts + i + 1) - __ldg(ts + i));

    const float* srow = seq    + ((size_t)b * 2048 + l) * 64;
    const float* c0   = coeffs + ((size_t)b * 2048 + i) * 64;

    // -------- phase A: z-half (16 values) for this thread's l --------
    float za[16];
#pragma unroll
    for (int j = 0; j < 16; j++) za[j] = 0.f;
    for (int Dd = 0; Dd < 64; Dd++) {
        float s = __ldg(srow + Dd);
        const float4* wg4 = (const float4*)(Wg + Dd * 32 + qh * 16);
#pragma unroll
        for (int c = 0; c < 4; c++) {
            float4 w = __ldg(wg4 + c);
            za[c*4+0] += s * w.x; za[c*4+1] += s * w.y;
            za[c*4+2] += s * w.z; za[c*4+3] += s * w.w;
        }
    }
#pragma unroll
    for (int j = 0; j < 16; j++) zs[lt * 33 + qh * 16 + j] = fmaxf(za[j], 0.f);
    __syncthreads();

    float z[32];
#pragma unroll
    for (int dd = 0; dd < 32; dd++) z[dd] = zs[lt * 33 + dd];

    float vacc[8];
#pragma unroll
    for (int q = 0; q < 8; q++) vacc[q] = 0.f;

    // -------- phase B: 8 Dd-tiles of 8, Wh tile in smem --------
    for (int tile = 0; tile < 8; tile++) {
        __syncthreads();
        for (int idx = tid; idx < 4096; idx += 256) {
            int dd = idx >> 7, rem = idx & 127;
            ws[idx] = __ldg(Wh + (size_t)dd * 1024 + tile * 128 + rem);
        }
        __syncthreads();

#pragma unroll
        for (int dloc = 0; dloc < 8; dloc++) {
            int Dd = tile * 8 + dloc;
            float der = (__ldg(c0 + 64 + Dd) - __ldg(c0 + Dd)) * invdt;
            unsigned long long h0 = 0ULL, h1 = 0ULL, h2 = 0ULL, h3 = 0ULL;
            const float* wbase = ws + dloc * 16 + qh * 8;
#pragma unroll
            for (int dd = 0; dd < 32; dd++) {
                unsigned long long zz;
                unsigned int zu = __float_as_uint(z[dd]);
                asm("mov.b64 %0, {%1, %1};" : "=l"(zz) : "r"(zu));
                const ulonglong2* wp = (const ulonglong2*)(wbase + dd * 128);
                ulonglong2 wA = wp[0], wB = wp[1];
                asm("fma.rn.f32x2 %0, %1, %2, %0;" : "+l"(h0) : "l"(wA.x), "l"(zz));
                asm("fma.rn.f32x2 %0, %1, %2, %0;" : "+l"(h1) : "l"(wA.y), "l"(zz));
                asm("fma.rn.f32x2 %0, %1, %2, %0;" : "+l"(h2) : "l"(wB.x), "l"(zz));
                asm("fma.rn.f32x2 %0, %1, %2, %0;" : "+l"(h3) : "l"(wB.y), "l"(zz));
            }
            unsigned int u0, u1;
            float hf[8];
            asm("mov.b64 {%0, %1}, %2;" : "=r"(u0), "=r"(u1) : "l"(h0));
            hf[0] = __uint_as_float(u0); hf[1] = __uint_as_float(u1);
            asm("mov.b64 {%0, %1}, %2;" : "=r"(u0), "=r"(u1) : "l"(h1));
            hf[2] = __uint_as_float(u0); hf[3] = __uint_as_float(u1);
            asm("mov.b64 {%0, %1}, %2;" : "=r"(u0), "=r"(u1) : "l"(h2));
            hf[4] = __uint_as_float(u0); hf[5] = __uint_as_float(u1);
            asm("mov.b64 {%0, %1}, %2;" : "=r"(u0), "=r"(u1) : "l"(h3));
            hf[6] = __uint_as_float(u0); hf[7] = __uint_as_float(u1);
#pragma unroll
            for (int q = 0; q < 8; q++) vacc[q] += fmaxf(hf[q], 0.f) * der;
        }
    }

#pragma unroll
    for (int q = 0; q < 8; q++)
        g_v[((size_t)b * 16 + qh * 8 + q) * 2048 + l] = vacc[q];
}

// ---------------- K2: 4-level Haar analysis per (b,k) -----------------------
__global__ void __launch_bounds__(256) k2_haar()
{
    __shared__ float buf[2048];
    int bk  = blockIdx.x;
    int tid = threadIdx.x;
    const float* src = g_v + (size_t)bk * 2048;
    for (int t = tid; t < 2048; t += 256) buf[t] = src[t];
    __syncthreads();

    int len = 2048;
    for (int lev = 0; lev < 4; lev++) {
        int half = len >> 1;
        int off  = lvl_off(lev);
        float ca_loc[4];
#pragma unroll
        for (int j = 0; j < 4; j++) {
            int t = tid + j * 256;
            if (t < half) {
                float a = buf[2*t], c = buf[2*t + 1];
                float ca = (a + c) * SQH, cd = (a - c) * SQH;
                g_det[off + (size_t)bk * half + t] = cd;
                ca_loc[j] = ca;
            }
        }
        __syncthreads();
#pragma unroll
        for (int j = 0; j < 4; j++) {
            int t = tid + j * 256;
            if (t < half) {
                buf[t] = ca_loc[j];
                g_app[off + (size_t)bk * half + t] = ca_loc[j];
            }
        }
        __syncthreads();
        len = half;
    }
}

// ---------------- K3: 3 x (128x128) matvec stack per (d,k) over 16 batches --
__global__ void __launch_bounds__(128) k3_dense(const float* __restrict__ dW)
{
    __shared__ float xs[16 * 128];
    int dk  = blockIdx.x;
    int kk  = dk & 15;
    int tid = threadIdx.x;
    int aoff = 458752;

#pragma unroll
    for (int b = 0; b < 16; b++)
        xs[tid * 16 + b] = g_app[aoff + (size_t)(b * 16 + kk) * 128 + tid];
    __syncthreads();

    for (int j = 0; j < 3; j++) {
        const float4* wrow4 = (const float4*)(dW + ((size_t)j * 512 + dk) * 16384 + (size_t)tid * 128);
        float acc[16];
#pragma unroll
        for (int b = 0; b < 16; b++) acc[b] = 0.f;
#pragma unroll 4
        for (int q4 = 0; q4 < 32; q4++) {
            float4 w = __ldg(wrow4 + q4);
            float wv[4] = {w.x, w.y, w.z, w.w};
#pragma unroll
            for (int c = 0; c < 4; c++) {
                const float4* x4 = (const float4*)(xs + (q4 * 4 + c) * 16);
#pragma unroll
                for (int b4 = 0; b4 < 4; b4++) {
                    float4 x = x4[b4];
                    acc[b4*4+0] += wv[c] * x.x; acc[b4*4+1] += wv[c] * x.y;
                    acc[b4*4+2] += wv[c] * x.z; acc[b4*4+3] += wv[c] * x.w;
                }
            }
        }
        __syncthreads();
#pragma unroll
        for (int b = 0; b < 16; b++) xs[tid * 16 + b] = acc[b];
        __syncthreads();
    }
#pragma unroll
    for (int b = 0; b < 16; b++)
        g_cur0[((size_t)dk * 16 + b) * 128 + tid] = xs[tid * 16 + b];
}

// ---------------- K4: LC + Haar reconstruction, one block per (b,d,k) -------
// Body is the R12-proven version (C=4 chunks). ONLY change vs R12:
// __launch_bounds__(256, 7) to lift the register-limited occupancy
// (R12: 40 regs -> 6 blocks/SM; target 37 regs -> 7 blocks/SM).
// Channel c data at chX[c*CS + 4 + t]; halo [2,3] and [4+Ll,5+Ll] = 0.
// wsm layout: [j][o][s][i][8] (taps 0..4 used, 5..7 zero).
template<int LEV>
__device__ __forceinline__ float* lc3_run(float* chA, float* chB,
    const float* __restrict__ wsm, const float* __restrict__ bsm, int tid)
{
    constexpr int Ll  = 2048 >> (LEV + 1);
    constexpr int SEG = 7 - LEV;
    constexpr int NCH = Ll >> 1;             // chunks of 4 over 2*Ll outputs

    float* src = chA; float* dst = chB;
#pragma unroll
    for (int j = 0; j < 3; j++) {
        const float* wj = wsm + j * 256;
        const float* bj = bsm + j * 16;
        for (int ch = tid; ch < NCH; ch += 256) {
            int ot0 = ch * 4;
            int o   = (ot0 >= Ll) ? 1 : 0;
            int t0  = ot0 - o * Ll;
            int s   = t0 >> SEG;
            float bb = bj[o * 8 + s];

            const float4* wp = (const float4*)(wj + (o * 8 + s) * 16);
            float4 wa0 = wp[0], wa1 = wp[1], wb0 = wp[2], wb1 = wp[3];
            float wA[5] = {wa0.x, wa0.y, wa0.z, wa0.w, wa1.x};
            float wB[5] = {wb0.x, wb0.y, wb0.z, wb0.w, wb1.x};

            const float4* s0 = (const float4*)(src + t0);
            const float4* s1 = (const float4*)(src + CS + t0);
            float4 a0 = s0[0], a1 = s0[1], a2 = s0[2];
            float4 e0 = s1[0], e1 = s1[1], e2 = s1[2];
            float y0[12] = {a0.x,a0.y,a0.z,a0.w, a1.x,a1.y,a1.z,a1.w, a2.x,a2.y,a2.z,a2.w};
            float y1[12] = {e0.x,e0.y,e0.z,e0.w, e1.x,e1.y,e1.z,e1.w, e2.x,e2.y,e2.z,e2.w};
            float out[4];
#pragma unroll
            for (int cc = 0; cc < 4; cc++) {
                float acc = bb;
#pragma unroll
                for (int f = 0; f < 5; f++)
                    acc += wA[f] * y0[cc + f + 2] + wB[f] * y1[cc + f + 2];
                out[cc] = fmaxf(acc, 0.f);
            }
            ((float4*)(dst + o * CS + 4 + t0))[0] =
                make_float4(out[0], out[1], out[2], out[3]);
        }
        __syncthreads();
        float* tp = src; src = dst; dst = tp;
    }
    return src;   // = chB (3 swaps)
}

template<int LEV>
__device__ __forceinline__ void k4_level(
    float* cur, float* chA, float* chB, float* wsm, float* bsm,
    const float* lcw, const float* lcb, int b, int dd, int kk, int tid)
{
    constexpr int Ll  = 2048 >> (LEV + 1);
    constexpr int OFF = 524288 - (524288 >> LEV);
    size_t cbase = (size_t)OFF + (size_t)(b * 16 + kk) * Ll;

    // zero halos of both buffers, both channels
    if (tid < 8) {
        int c = tid >> 2, u = tid & 3;
        int idx = c * CS + ((u < 2) ? (2 + u) : (Ll + 2 + u));
        chA[idx] = 0.f; chB[idx] = 0.f;
    }
    // stage inputs: channel 0 = detail, channel 1 = approx (scalar, R9 form)
    for (int t = tid; t < Ll; t += 256) {
        chA[4 + t]      = g_det[cbase + t];
        chA[CS + 4 + t] = g_app[cbase + t];
    }
    // stage weights (padded to 8 taps) + biases
    for (int idx = tid; idx < 768; idx += 256) {
        int j   = idx >> 8;
        int rem = idx & 255;
        int os  = rem >> 4;
        int ii  = (rem >> 3) & 1;
        int f   = rem & 7;
        int o   = os >> 3, s = os & 7;
        float v = 0.f;
        if (f < 5)
            v = __ldg(lcw + (size_t)(((LEV * 3 + j) * 32 + dd) * 16 + kk) * 160
                          + ((o * 2 + ii) * 8 + s) * 5 + f);
        wsm[idx] = v;
    }
    if (tid < 48) {
        int j = tid >> 4, r = tid & 15;
        bsm[tid] = __ldg(lcb + (size_t)(((LEV * 3 + j) * 32 + dd) * 16 + kk) * 16 + r);
    }
    __syncthreads();

    float* src = lc3_run<LEV>(chA, chB, wsm, bsm, tid);

    // X[approx] += cur ; haar_rec -> chA (flat, float2), then into cur
    for (int t = tid; t < Ll; t += 256) {
        float cAv = src[CS + 4 + t] + cur[t];
        float cDv = src[4 + t];
        ((float2*)chA)[t] = make_float2((cAv + cDv) * SQH, (cAv - cDv) * SQH);
    }
    __syncthreads();
    for (int i = tid; i < (Ll >> 1); i += 256)
        ((float4*)cur)[i] = ((const float4*)chA)[i];
    __syncthreads();
}

__global__ void __launch_bounds__(256, 7) k4_rec(
    const float* __restrict__ lcw, const float* __restrict__ lcb)
{
    __shared__ __align__(16) float cur[2048];
    __shared__ __align__(16) float chA[2 * CS];
    __shared__ __align__(16) float chB[2 * CS];
    __shared__ __align__(16) float wsm[768];
    __shared__ float bsm[48];

    int bid = blockIdx.x;
    int dd  = bid & 31;
    int kk  = (bid >> 5) & 15;
    int b   = bid >> 9;
    int tid = threadIdx.x;

    if (tid < 128)
        cur[tid] = g_cur0[((size_t)(dd * 16 + kk) * 16 + b) * 128 + tid];

    k4_level<3>(cur, chA, chB, wsm, bsm, lcw, lcb, b, dd, kk, tid);
    k4_level<2>(cur, chA, chB, wsm, bsm, lcw, lcb, b, dd, kk, tid);
    k4_level<1>(cur, chA, chB, wsm, bsm, lcw, lcb, b, dd, kk, tid);
    k4_level<0>(cur, chA, chB, wsm, bsm, lcw, lcb, b, dd, kk, tid);

    float* dst = g_curk + ((size_t)(b * 32 + dd) * 16 + kk) * 2048;
    for (int i = tid; i < 512; i += 256)
        ((float4*)dst)[i] = ((const float4*)cur)[i];
}

// ---------------- K5: sum over k, then U[b,l,:] = out[b,:,l]^T @ Wrev -------
// (R9-proven scalar version)
__global__ void __launch_bounds__(256) k5_out(
    const float* __restrict__ Wrev, float* __restrict__ U)
{
    __shared__ float ws[2048];
    __shared__ float os[32][132];
    int b   = blockIdx.y;
    int l0  = blockIdx.x * 128;
    int tid = threadIdx.x;

    for (int i = tid; i < 2048; i += 256) ws[i] = __ldg(Wrev + i);
    for (int i = tid; i < 4096; i += 256) {
        int dd = i >> 7, lt = i & 127;
        const float* p = g_curk + ((size_t)(b * 32 + dd) * 16) * 2048 + l0 + lt;
        float s = 0.f;
#pragma unroll
        for (int kk = 0; kk < 16; kk++) s += p[(size_t)kk * 2048];
        os[dd][lt] = s;
    }
    __syncthreads();

    int lt = tid >> 1, half = tid & 1;
    float acc[32];
#pragma unroll
    for (int j = 0; j < 32; j++) acc[j] = 0.f;
    for (int dd = 0; dd < 32; dd++) {
        float xv = os[dd][lt];
        const float* w = ws + dd * 64 + half * 32;
#pragma unroll
        for (int j = 0; j < 32; j++) acc[j] += xv * w[j];
    }
    float* dst = U + ((size_t)b * 2048 + l0 + lt) * 64 + half * 32;
#pragma unroll
    for (int j = 0; j < 32; j++) dst[j] = acc[j];
}

// ---------------- launch ----------------------------------------------------
extern "C" void kernel_launch(void* const* d_in, const int* in_sizes, int n_in,
                              void* d_out, int out_size)
{
    const float* seq    = (const float*)d_in[0];
    const float* coeffs = (const float*)d_in[1];
    const float* time_  = (const float*)d_in[2];
    const float* tstep  = (const float*)d_in[3];
    const float* Wg     = (const float*)d_in[4];
    const float* Wh     = (const float*)d_in[5];
    const float* dW     = (const float*)d_in[6];
    const float* lcw    = (const float*)d_in[7];
    const float* lcb    = (const float*)d_in[8];
    const float* Wrev   = (const float*)d_in[9];
    float* U = (float*)d_out;

    k1_front<<<256, 256>>>(seq, coeffs, time_, tstep, Wg, Wh);
    k2_haar<<<256, 256>>>();
    k3_dense<<<512, 128>>>(dW);
    k4_rec<<<8192, 256>>>(lcw, lcb);
    k5_out<<<dim3(16, 16), 256>>>(Wrev, U);
}